// round 1
// baseline (speedup 1.0000x reference)
#include <cuda_runtime.h>
#include <math.h>

// Problem: B=4, N=4096, D=256
//   scores = (V V^T) / 16 ; edges = softsign(scores)
//   dstate = edges @ state ; dval = edges @ V
// Fused flash-style: never materialize scores in HBM.

#define BATCH 4
#define NN    4096
#define DD    256
#define BM    64     // i-tile rows per block
#define BJ    64     // j-tile
#define THREADS 256
#define V_STRIDE 257   // padded smem stride (odd multiple avoids bank conflicts)
#define E_STRIDE 65

// smem layout (floats): Vi[BM*V_STRIDE] | Vj[BJ*V_STRIDE] | E[BM*E_STRIDE] | Ss[BJ]
#define SMEM_FLOATS (BM*V_STRIDE + BJ*V_STRIDE + BM*E_STRIDE + BJ)

__global__ __launch_bounds__(THREADS, 1)
void prop_kernel(const float* __restrict__ val,
                 const float* __restrict__ state,
                 float* __restrict__ dstate,
                 float* __restrict__ dval)
{
    extern __shared__ float smem[];
    float* Vi = smem;
    float* Vj = Vi + BM * V_STRIDE;
    float* E  = Vj + BJ * V_STRIDE;
    float* Ss = E  + BM * E_STRIDE;

    const int b   = blockIdx.y;
    const int i0  = blockIdx.x * BM;
    const int tid = threadIdx.x;
    const int tx  = tid & 15;   // 0..15
    const int ty  = tid >> 4;   // 0..15

    const float* valb = val + (size_t)b * NN * DD;

    // ---- load Vi tile (64 x 256) once, float4 global, scalar smem stores (padded) ----
    for (int e = tid; e < BM * (DD / 4); e += THREADS) {
        int r  = e >> 6;        // DD/4 = 64 float4 per row
        int k4 = e & 63;
        float4 v = *(const float4*)(valb + (size_t)(i0 + r) * DD + k4 * 4);
        float* d = Vi + r * V_STRIDE + k4 * 4;
        d[0] = v.x; d[1] = v.y; d[2] = v.z; d[3] = v.w;
    }

    // accumulators: thread owns rows {ty*4+r}, cols {tx + 16*c}
    float acc[4][16];
    #pragma unroll
    for (int r = 0; r < 4; r++)
        #pragma unroll
        for (int c = 0; c < 16; c++) acc[r][c] = 0.0f;
    float accs[4] = {0.f, 0.f, 0.f, 0.f};

    const float scale = 0.0625f;  // 256^-0.5

    for (int j0 = 0; j0 < NN; j0 += BJ) {
        __syncthreads();  // protect Vj/E/Ss reuse from previous iter

        // ---- load Vj tile + state slice ----
        for (int e = tid; e < BJ * (DD / 4); e += THREADS) {
            int r  = e >> 6;
            int k4 = e & 63;
            float4 v = *(const float4*)(valb + (size_t)(j0 + r) * DD + k4 * 4);
            float* d = Vj + r * V_STRIDE + k4 * 4;
            d[0] = v.x; d[1] = v.y; d[2] = v.z; d[3] = v.w;
        }
        if (tid < BJ) Ss[tid] = state[(size_t)b * NN + j0 + tid];
        __syncthreads();

        // ---- Phase A: S(64x64) = Vi · Vj^T ; thread: rows ty*4+{0..3}, cols tx+16*{0..3}
        float s00=0,s01=0,s02=0,s03=0;
        float s10=0,s11=0,s12=0,s13=0;
        float s20=0,s21=0,s22=0,s23=0;
        float s30=0,s31=0,s32=0,s33=0;
        {
            const float* ai = Vi + (ty * 4) * V_STRIDE;
            const float* bj = Vj + tx * V_STRIDE;
            #pragma unroll 4
            for (int k = 0; k < DD; k++) {
                float a0 = ai[k];
                float a1 = ai[1 * V_STRIDE + k];
                float a2 = ai[2 * V_STRIDE + k];
                float a3 = ai[3 * V_STRIDE + k];
                float b0 = bj[k];
                float b1 = bj[16 * V_STRIDE + k];
                float b2 = bj[32 * V_STRIDE + k];
                float b3 = bj[48 * V_STRIDE + k];
                s00 += a0*b0; s01 += a0*b1; s02 += a0*b2; s03 += a0*b3;
                s10 += a1*b0; s11 += a1*b1; s12 += a1*b2; s13 += a1*b3;
                s20 += a2*b0; s21 += a2*b1; s22 += a2*b2; s23 += a2*b3;
                s30 += a3*b0; s31 += a3*b1; s32 += a3*b2; s33 += a3*b3;
            }
        }
        // softsign + write E (rows ty*4+r, cols tx+16*c)
        {
            float sv[4][4] = {{s00,s01,s02,s03},{s10,s11,s12,s13},
                              {s20,s21,s22,s23},{s30,s31,s32,s33}};
            #pragma unroll
            for (int r = 0; r < 4; r++)
                #pragma unroll
                for (int c = 0; c < 4; c++) {
                    float x = sv[r][c] * scale;
                    E[(ty*4 + r) * E_STRIDE + tx + 16*c] = x / (1.0f + fabsf(x));
                }
        }
        __syncthreads();

        // ---- Phase B: acc += E(64x64) @ Vj(64x256), accs += E @ state ----
        #pragma unroll 2
        for (int kk = 0; kk < BJ; kk++) {
            float e0 = E[(ty*4 + 0) * E_STRIDE + kk];
            float e1 = E[(ty*4 + 1) * E_STRIDE + kk];
            float e2 = E[(ty*4 + 2) * E_STRIDE + kk];
            float e3 = E[(ty*4 + 3) * E_STRIDE + kk];
            float sv = Ss[kk];
            accs[0] += e0 * sv;
            accs[1] += e1 * sv;
            accs[2] += e2 * sv;
            accs[3] += e3 * sv;
            const float* vr = Vj + kk * V_STRIDE;
            #pragma unroll
            for (int c = 0; c < 16; c++) {
                float v = vr[tx + 16*c];
                acc[0][c] += e0 * v;
                acc[1][c] += e1 * v;
                acc[2][c] += e2 * v;
                acc[3][c] += e3 * v;
            }
        }
    }

    // ---- epilogue ----
    float* dstate_b = dstate + (size_t)b * NN;
    float* dval_b   = dval   + (size_t)b * NN * DD;
    if (tx == 0) {
        #pragma unroll
        for (int r = 0; r < 4; r++) dstate_b[i0 + ty*4 + r] = accs[r];
    }
    #pragma unroll
    for (int r = 0; r < 4; r++) {
        float* out_row = dval_b + (size_t)(i0 + ty*4 + r) * DD;
        #pragma unroll
        for (int c = 0; c < 16; c++) out_row[tx + 16*c] = acc[r][c];
    }
}

extern "C" void kernel_launch(void* const* d_in, const int* in_sizes, int n_in,
                              void* d_out, int out_size)
{
    const float* val   = (const float*)d_in[0];   // [B, N, D]
    const float* state = (const float*)d_in[1];   // [B, N]
    float* dstate = (float*)d_out;                // [B, N]      (first B*N elements)
    float* dval   = dstate + (size_t)BATCH * NN;  // [B, N, D]   (remaining)

    (void)in_sizes; (void)n_in; (void)out_size;

    size_t smem_bytes = SMEM_FLOATS * sizeof(float);
    cudaFuncSetAttribute(prop_kernel,
                         cudaFuncAttributeMaxDynamicSharedMemorySize,
                         (int)smem_bytes);

    dim3 grid(NN / BM, BATCH);
    prop_kernel<<<grid, THREADS, smem_bytes>>>(val, state, dstate, dval);
}

// round 3
// speedup vs baseline: 4.3246x; 4.3246x over previous
#include <cuda_runtime.h>
#include <cuda_bf16.h>
#include <cstdint>

// B=4, N=4096, D=256
// scores = (V V^T)/16 ; edges = softsign(scores)
// dstate = edges @ state ; dval = edges @ val
// Split-bf16 (hi/lo, 3-term) HMMA flash kernel. Base-ISA only (no tcgen05).

#define BATCH 4
#define NN 4096
#define DD 256
#define BM 128
#define BJ 64
#define THREADS 256
#define ROWB 528               // 33 x 16B chunks per 256-bf16 row (conflict-free)

static constexpr uint32_t S_VIH = 0;
static constexpr uint32_t S_VIL = 128u * ROWB;             //  67584
static constexpr uint32_t S_VJH = 2u * 128u * ROWB;        // 135168
static constexpr uint32_t S_VJL = S_VJH + 64u * ROWB;      // 168960
static constexpr uint32_t S_ST  = S_VJL + 64u * ROWB;      // 202752
static constexpr uint32_t SMEM_BYTES = S_ST + 64u * 4u;    // 203008

// ---------------- helpers ----------------
__device__ __forceinline__ uint32_t smem_u32(const void* p) {
    uint32_t a;
    asm("{ .reg .u64 t; cvta.to.shared.u64 t, %1; cvt.u32.u64 %0, t; }" : "=r"(a) : "l"(p));
    return a;
}
__device__ __forceinline__ void ldm_x4(uint32_t* r, uint32_t addr) {
    asm volatile("ldmatrix.sync.aligned.m8n8.x4.shared.b16 {%0,%1,%2,%3}, [%4];"
        : "=r"(r[0]), "=r"(r[1]), "=r"(r[2]), "=r"(r[3]) : "r"(addr));
}
__device__ __forceinline__ void ldm_x4_t(uint32_t* r, uint32_t addr) {
    asm volatile("ldmatrix.sync.aligned.m8n8.x4.trans.shared.b16 {%0,%1,%2,%3}, [%4];"
        : "=r"(r[0]), "=r"(r[1]), "=r"(r[2]), "=r"(r[3]) : "r"(addr));
}
__device__ __forceinline__ void mma16816(float* c, const uint32_t* a, const uint32_t* b) {
    asm volatile("mma.sync.aligned.m16n8k16.row.col.f32.bf16.bf16.f32 "
        "{%0,%1,%2,%3}, {%4,%5,%6,%7}, {%8,%9}, {%0,%1,%2,%3};"
        : "+f"(c[0]), "+f"(c[1]), "+f"(c[2]), "+f"(c[3])
        : "r"(a[0]), "r"(a[1]), "r"(a[2]), "r"(a[3]), "r"(b[0]), "r"(b[1]));
}
// hi = truncate-to-bf16 of (x,y) packed; lo = rn(x - hi_x), rn(y - hi_y) packed
__device__ __forceinline__ uint32_t hi2(float x, float y) {
    return __byte_perm(__float_as_uint(x), __float_as_uint(y), 0x7632);
}
__device__ __forceinline__ uint32_t lo2(float x, float y) {
    float hx = __uint_as_float(__float_as_uint(x) & 0xFFFF0000u);
    float hy = __uint_as_float(__float_as_uint(y) & 0xFFFF0000u);
    __nv_bfloat162 t = __floats2bfloat162_rn(x - hx, y - hy);
    return *reinterpret_cast<uint32_t*>(&t);
}
__device__ __forceinline__ void split8(float4 p0, float4 p1, uint4& hi, uint4& lo) {
    hi.x = hi2(p0.x, p0.y); lo.x = lo2(p0.x, p0.y);
    hi.y = hi2(p0.z, p0.w); lo.y = lo2(p0.z, p0.w);
    hi.z = hi2(p1.x, p1.y); lo.z = lo2(p1.x, p1.y);
    hi.w = hi2(p1.z, p1.w); lo.w = lo2(p1.z, p1.w);
}

__global__ __launch_bounds__(THREADS, 1)
void prop_hmma(const float* __restrict__ val, const float* __restrict__ state,
               float* __restrict__ dstate, float* __restrict__ dval)
{
    extern __shared__ char smem[];
    const uint32_t sb = smem_u32(smem);
    const int tid = threadIdx.x, l = tid & 31, wid = tid >> 5;
    const int b = blockIdx.y, i0 = blockIdx.x * BM;
    const int mrow = wid * 16;
    const float* valb = val + (size_t)b * NN * DD;

    // ---- fill Vi (128 x 256 fp32 -> hi/lo bf16, swizzle-free padded layout) ----
    #pragma unroll
    for (int k = 0; k < 16; k++) {
        int u = tid + 256 * k;                 // unit = 8 f32 -> one 16B chunk
        int row = u >> 5, cu = u & 31;
        const float4* p = (const float4*)(valb + (size_t)(i0 + row) * DD + cu * 8);
        float4 p0 = p[0], p1 = p[1];
        uint4 hi, lo; split8(p0, p1, hi, lo);
        *(uint4*)(smem + S_VIH + row * ROWB + cu * 16) = hi;
        *(uint4*)(smem + S_VIL + row * ROWB + cu * 16) = lo;
    }

    // per-thread ldmatrix address components
    const uint32_t offA  = (uint32_t)((l & 15) * ROWB + (l >> 4) * 16);          // A & trans-B pattern
    const uint32_t offBn = (uint32_t)(((l & 7) + ((l & 16) ? 8 : 0)) * ROWB + ((l >> 3) & 1) * 16);
    const uint32_t viH = sb + S_VIH + mrow * ROWB + offA;
    const uint32_t viL = sb + S_VIL + mrow * ROWB + offA;
    const uint32_t vjB = sb + S_VJH + offBn;     // phase A B (non-trans), hi; +64*ROWB = lo
    const uint32_t vjT = sb + S_VJH + offA;      // phase B B (trans), hi;    +64*ROWB = lo
    const float* stp = (const float*)(smem + S_ST);

    float dacc[32][4];
    #pragma unroll
    for (int t = 0; t < 32; t++) { dacc[t][0] = dacc[t][1] = dacc[t][2] = dacc[t][3] = 0.f; }
    float ds0 = 0.f, ds1 = 0.f;
    const float scale = 0.0625f;
    const int c0 = 2 * (l & 3);

    for (int it = 0; it < NN / BJ; it++) {
        __syncthreads();                    // prev phase-B smem reads done
        const int j0 = it * BJ;
        // ---- fill Vj (64 x 256) + state slice ----
        #pragma unroll
        for (int k = 0; k < 8; k++) {
            int u = tid + 256 * k;
            int row = u >> 5, cu = u & 31;
            const float4* p = (const float4*)(valb + (size_t)(j0 + row) * DD + cu * 8);
            float4 p0 = p[0], p1 = p[1];
            uint4 hi, lo; split8(p0, p1, hi, lo);
            *(uint4*)(smem + S_VJH + row * ROWB + cu * 16) = hi;
            *(uint4*)(smem + S_VJL + row * ROWB + cu * 16) = lo;
        }
        if (tid < BJ) ((float*)(smem + S_ST))[tid] = state[(size_t)b * NN + j0 + tid];
        __syncthreads();

        // ---- Phase A: S[16 x 64] per warp, K = 256, 3-term split ----
        float sacc[8][4];
        #pragma unroll
        for (int t = 0; t < 8; t++) { sacc[t][0] = sacc[t][1] = sacc[t][2] = sacc[t][3] = 0.f; }

        #pragma unroll
        for (int s = 0; s < 16; s++) {
            uint32_t ah[4], al[4];
            ldm_x4(ah, viH + s * 32);
            ldm_x4(al, viL + s * 32);
            #pragma unroll
            for (int q = 0; q < 4; q++) {
                uint32_t bh[4], bl[4];
                ldm_x4(bh, vjB + q * (16 * ROWB) + s * 32);
                ldm_x4(bl, vjB + 64 * ROWB + q * (16 * ROWB) + s * 32);
                mma16816(sacc[2 * q],     ah, bh + 0);
                mma16816(sacc[2 * q],     ah, bl + 0);
                mma16816(sacc[2 * q],     al, bh + 0);
                mma16816(sacc[2 * q + 1], ah, bh + 2);
                mma16816(sacc[2 * q + 1], ah, bl + 2);
                mma16816(sacc[2 * q + 1], al, bh + 2);
            }
        }

        // ---- epilogue: softsign (fp32), dstate partial, E -> a-frags (in-register) ----
        uint32_t eh[4][4], el[4][4];
        #pragma unroll
        for (int t = 0; t < 8; t++) {
            float f0 = sacc[t][0] * scale, f1 = sacc[t][1] * scale;
            float f2 = sacc[t][2] * scale, f3 = sacc[t][3] * scale;
            float e0 = __fdividef(f0, 1.0f + fabsf(f0));
            float e1 = __fdividef(f1, 1.0f + fabsf(f1));
            float e2 = __fdividef(f2, 1.0f + fabsf(f2));
            float e3 = __fdividef(f3, 1.0f + fabsf(f3));
            float sA = stp[8 * t + c0], sB = stp[8 * t + c0 + 1];
            ds0 += e0 * sA + e1 * sB;
            ds1 += e2 * sA + e3 * sB;
            int kt = t >> 1, h = (t & 1) * 2;
            eh[kt][h]     = hi2(e0, e1);
            eh[kt][h + 1] = hi2(e2, e3);
            el[kt][h]     = lo2(e0, e1);
            el[kt][h + 1] = lo2(e2, e3);
        }

        // ---- Phase B: dval[16 x 256] += E @ Vj, K = 64, 3-term split ----
        #pragma unroll
        for (int kt = 0; kt < 4; kt++) {
            uint32_t tb = vjT + kt * (16 * ROWB);
            #pragma unroll
            for (int nt2 = 0; nt2 < 16; nt2++) {
                uint32_t bh[4], bl[4];
                ldm_x4_t(bh, tb + nt2 * 32);
                ldm_x4_t(bl, tb + 64 * ROWB + nt2 * 32);
                mma16816(dacc[2 * nt2],     eh[kt], bh + 0);
                mma16816(dacc[2 * nt2],     eh[kt], bl + 0);
                mma16816(dacc[2 * nt2],     el[kt], bh + 0);
                mma16816(dacc[2 * nt2 + 1], eh[kt], bh + 2);
                mma16816(dacc[2 * nt2 + 1], eh[kt], bl + 2);
                mma16816(dacc[2 * nt2 + 1], el[kt], bh + 2);
            }
        }
    }

    // ---- write dval ----
    {
        const int row = i0 + mrow + (l >> 2);
        float* d0 = dval + (size_t)b * NN * DD + (size_t)row * DD;
        float* d1 = d0 + 8 * DD;
        #pragma unroll
        for (int nt = 0; nt < 32; nt++) {
            int c = 8 * nt + c0;
            *(float2*)(d0 + c) = make_float2(dacc[nt][0], dacc[nt][1]);
            *(float2*)(d1 + c) = make_float2(dacc[nt][2], dacc[nt][3]);
        }
    }
    // ---- dstate: reduce over the 4 lanes sharing a row ----
    ds0 += __shfl_xor_sync(0xFFFFFFFFu, ds0, 1);
    ds0 += __shfl_xor_sync(0xFFFFFFFFu, ds0, 2);
    ds1 += __shfl_xor_sync(0xFFFFFFFFu, ds1, 1);
    ds1 += __shfl_xor_sync(0xFFFFFFFFu, ds1, 2);
    if ((l & 3) == 0) {
        int r = i0 + mrow + (l >> 2);
        dstate[(size_t)b * NN + r]     = ds0;
        dstate[(size_t)b * NN + r + 8] = ds1;
    }
}

extern "C" void kernel_launch(void* const* d_in, const int* in_sizes, int n_in,
                              void* d_out, int out_size)
{
    const float* val   = (const float*)d_in[0];   // [B, N, D]
    const float* state = (const float*)d_in[1];   // [B, N]
    float* dstate = (float*)d_out;                // [B, N]
    float* dval   = dstate + (size_t)BATCH * NN;  // [B, N, D]
    (void)in_sizes; (void)n_in; (void)out_size;

    cudaFuncSetAttribute(prop_hmma,
                         cudaFuncAttributeMaxDynamicSharedMemorySize, (int)SMEM_BYTES);

    dim3 grid(NN / BM, BATCH);
    prop_hmma<<<grid, THREADS, SMEM_BYTES>>>(val, state, dstate, dval);
}

// round 4
// speedup vs baseline: 4.3254x; 1.0002x over previous
#include <cuda_runtime.h>
#include <cuda_bf16.h>
#include <cstdint>

// B=4, N=4096, D=256
// scores = (V V^T)/16 ; edges = softsign(scores)
// dstate = edges @ state ; dval = edges @ val
// Split-bf16 (hi/lo, 3-term) HMMA flash kernel with pre-split + cp.async
// double-buffered j-pipeline.

#define BATCH 4
#define NN 4096
#define DD 256
#define BM 128
#define BJH 32            // half j-tile (pipeline stage)
#define NHALF (NN / BJH)  // 128
#define THREADS 256
#define ROWB 528          // 33 x 16B per 256-bf16 row (conflict-free padding)

// smem layout (bytes)
static constexpr uint32_t S_VIH = 0;                       // Vi hi: 128 rows
static constexpr uint32_t S_VIL = 128u * ROWB;             //  67584: Vi lo
static constexpr uint32_t S_VJ0 = 2u * 128u * ROWB;        // 135168: buf0 (hi 32 rows | lo 32 rows)
static constexpr uint32_t S_VJ1 = S_VJ0 + 64u * ROWB;      // 168960: buf1
static constexpr uint32_t VJ_LO = 32u * ROWB;              //  16896: lo offset within buffer
static constexpr uint32_t S_ST0 = S_VJ1 + 64u * ROWB;      // 202752: state slice buf0 (128B)
static constexpr uint32_t S_ST1 = S_ST0 + 128u;            // 202880
static constexpr uint32_t SMEM_BYTES = S_ST1 + 128u;       // 203008

// ---------------- device scratch: pre-split bf16 hi/lo ----------------
__device__ __nv_bfloat16 g_vhi[(size_t)BATCH * NN * DD];
__device__ __nv_bfloat16 g_vlo[(size_t)BATCH * NN * DD];

// ---------------- helpers ----------------
__device__ __forceinline__ uint32_t smem_u32(const void* p) {
    uint32_t a;
    asm("{ .reg .u64 t; cvta.to.shared.u64 t, %1; cvt.u32.u64 %0, t; }" : "=r"(a) : "l"(p));
    return a;
}
__device__ __forceinline__ void cpa16(uint32_t dst, const void* src) {
    asm volatile("cp.async.cg.shared.global [%0], [%1], 16;" :: "r"(dst), "l"(src) : "memory");
}
#define CP_COMMIT() asm volatile("cp.async.commit_group;" ::: "memory")
#define CP_WAIT1()  asm volatile("cp.async.wait_group 1;" ::: "memory")

__device__ __forceinline__ void ldm_x4(uint32_t* r, uint32_t addr) {
    asm volatile("ldmatrix.sync.aligned.m8n8.x4.shared.b16 {%0,%1,%2,%3}, [%4];"
        : "=r"(r[0]), "=r"(r[1]), "=r"(r[2]), "=r"(r[3]) : "r"(addr));
}
__device__ __forceinline__ void ldm_x4_t(uint32_t* r, uint32_t addr) {
    asm volatile("ldmatrix.sync.aligned.m8n8.x4.trans.shared.b16 {%0,%1,%2,%3}, [%4];"
        : "=r"(r[0]), "=r"(r[1]), "=r"(r[2]), "=r"(r[3]) : "r"(addr));
}
__device__ __forceinline__ void mma16816(float* c, const uint32_t* a, const uint32_t* b) {
    asm volatile("mma.sync.aligned.m16n8k16.row.col.f32.bf16.bf16.f32 "
        "{%0,%1,%2,%3}, {%4,%5,%6,%7}, {%8,%9}, {%0,%1,%2,%3};"
        : "+f"(c[0]), "+f"(c[1]), "+f"(c[2]), "+f"(c[3])
        : "r"(a[0]), "r"(a[1]), "r"(a[2]), "r"(a[3]), "r"(b[0]), "r"(b[1]));
}
__device__ __forceinline__ uint32_t hi2(float x, float y) {
    return __byte_perm(__float_as_uint(x), __float_as_uint(y), 0x7632);
}
__device__ __forceinline__ uint32_t lo2(float x, float y) {
    float hx = __uint_as_float(__float_as_uint(x) & 0xFFFF0000u);
    float hy = __uint_as_float(__float_as_uint(y) & 0xFFFF0000u);
    __nv_bfloat162 t = __floats2bfloat162_rn(x - hx, y - hy);
    return *reinterpret_cast<uint32_t*>(&t);
}

// ---------------- pre-kernel: fp32 -> bf16 hi/lo split ----------------
__global__ __launch_bounds__(256) void split_kernel(const float* __restrict__ val) {
    const int b = blockIdx.y, n0 = blockIdx.x * 64;
    const size_t base = ((size_t)b * NN + n0) * DD;
    // 64 rows x 256 cols = 16384 elems; 4096 float4 units; 16 per thread
    #pragma unroll
    for (int k = 0; k < 16; k++) {
        int u = threadIdx.x + 256 * k;
        float4 v = *(const float4*)(val + base + (size_t)u * 4);
        uint32_t h0 = hi2(v.x, v.y), h1 = hi2(v.z, v.w);
        uint32_t l0 = lo2(v.x, v.y), l1 = lo2(v.z, v.w);
        *(uint2*)(g_vhi + base + (size_t)u * 4) = make_uint2(h0, h1);
        *(uint2*)(g_vlo + base + (size_t)u * 4) = make_uint2(l0, l1);
    }
}

// ---------------- main kernel ----------------
__global__ __launch_bounds__(THREADS, 1)
void prop_hmma(const float* __restrict__ state,
               float* __restrict__ dstate, float* __restrict__ dval)
{
    extern __shared__ char smem[];
    const uint32_t sb = smem_u32(smem);
    const int tid = threadIdx.x, l = tid & 31, wid = tid >> 5;
    const int b = blockIdx.y, i0 = blockIdx.x * BM;
    const int mrow = wid * 16;
    const size_t vbase = (size_t)b * NN * DD;

    // ---- prologue: Vi fill (group 0, includes j-fill 0) ----
    {
        // Vi: 128 rows x 32 chunks x 2 (hi/lo) = 8192 chunks; 32 per thread
        #pragma unroll
        for (int k = 0; k < 32; k++) {
            int u = tid + 256 * k;
            int row = u >> 6, rem = u & 63;
            int half = rem >> 5, ch = rem & 31;
            uint32_t dst = sb + (half ? S_VIL : S_VIH) + (uint32_t)(row * ROWB + ch * 16);
            const __nv_bfloat16* src = (half ? g_vlo : g_vhi) + vbase + (size_t)(i0 + row) * DD + ch * 8;
            cpa16(dst, src);
        }
        // j-fill half 0 into buf0: 32 rows x 32 chunks x 2 = 2048 chunks; 8/thread
        #pragma unroll
        for (int k = 0; k < 8; k++) {
            int u = tid + 256 * k;
            int row = u >> 6, rem = u & 63;
            int half = rem >> 5, ch = rem & 31;
            uint32_t dst = sb + S_VJ0 + (half ? VJ_LO : 0u) + (uint32_t)(row * ROWB + ch * 16);
            const __nv_bfloat16* src = (half ? g_vlo : g_vhi) + vbase + (size_t)row * DD + ch * 8;
            cpa16(dst, src);
        }
        if (tid < 8) cpa16(sb + S_ST0 + tid * 16, state + (size_t)b * NN + tid * 4);
        CP_COMMIT();
    }

    // per-thread ldmatrix offsets
    const uint32_t offA  = (uint32_t)((l & 15) * ROWB + (l >> 4) * 16);
    const uint32_t offBn = (uint32_t)(((l & 7) + ((l & 16) ? 8 : 0)) * ROWB + ((l >> 3) & 1) * 16);
    const uint32_t viH = sb + S_VIH + mrow * ROWB + offA;
    const uint32_t viL = sb + S_VIL + mrow * ROWB + offA;

    float dacc[32][4];
    #pragma unroll
    for (int t = 0; t < 32; t++) { dacc[t][0] = dacc[t][1] = dacc[t][2] = dacc[t][3] = 0.f; }
    float ds0 = 0.f, ds1 = 0.f;
    const float scale = 0.0625f;
    const int c0 = 2 * (l & 3);

    for (int h = 0; h < NHALF; h++) {
        // ---- issue fill(h+1) into buf[(h+1)&1] ----
        {
            int hn = h + 1;
            if (hn < NHALF) {
                const int j0 = hn * BJH;
                uint32_t bufb = sb + ((hn & 1) ? S_VJ1 : S_VJ0);
                #pragma unroll
                for (int k = 0; k < 8; k++) {
                    int u = tid + 256 * k;
                    int row = u >> 6, rem = u & 63;
                    int half = rem >> 5, ch = rem & 31;
                    uint32_t dst = bufb + (half ? VJ_LO : 0u) + (uint32_t)(row * ROWB + ch * 16);
                    const __nv_bfloat16* src = (half ? g_vlo : g_vhi) + vbase + (size_t)(j0 + row) * DD + ch * 8;
                    cpa16(dst, src);
                }
                if (tid < 8)
                    cpa16(sb + ((hn & 1) ? S_ST1 : S_ST0) + tid * 16,
                          state + (size_t)b * NN + j0 + tid * 4);
            }
            CP_COMMIT();
        }
        CP_WAIT1();          // fill(h) complete
        __syncthreads();     // visible to all warps

        const uint32_t bufb = sb + ((h & 1) ? S_VJ1 : S_VJ0);
        const uint32_t vjB = bufb + offBn;
        const uint32_t vjT = bufb + offA;
        const float* stp = (const float*)(smem + ((h & 1) ? S_ST1 : S_ST0));

        // ---- Phase A: S[16 x 32] per warp, K = 256, 3-term split ----
        float sacc[4][4];
        #pragma unroll
        for (int t = 0; t < 4; t++) { sacc[t][0] = sacc[t][1] = sacc[t][2] = sacc[t][3] = 0.f; }

        #pragma unroll
        for (int s = 0; s < 16; s++) {
            uint32_t ah[4], al[4];
            ldm_x4(ah, viH + s * 32);
            ldm_x4(al, viL + s * 32);
            #pragma unroll
            for (int q = 0; q < 2; q++) {
                uint32_t bh[4], bl[4];
                ldm_x4(bh, vjB + q * (16 * ROWB) + s * 32);
                ldm_x4(bl, vjB + VJ_LO + q * (16 * ROWB) + s * 32);
                mma16816(sacc[2 * q],     ah, bh + 0);
                mma16816(sacc[2 * q],     ah, bl + 0);
                mma16816(sacc[2 * q],     al, bh + 0);
                mma16816(sacc[2 * q + 1], ah, bh + 2);
                mma16816(sacc[2 * q + 1], ah, bl + 2);
                mma16816(sacc[2 * q + 1], al, bh + 2);
            }
        }

        // ---- epilogue: softsign (fp32), dstate partial, E -> a-frags ----
        uint32_t eh[2][4], el[2][4];
        #pragma unroll
        for (int t = 0; t < 4; t++) {
            float f0 = sacc[t][0] * scale, f1 = sacc[t][1] * scale;
            float f2 = sacc[t][2] * scale, f3 = sacc[t][3] * scale;
            float e0 = __fdividef(f0, 1.0f + fabsf(f0));
            float e1 = __fdividef(f1, 1.0f + fabsf(f1));
            float e2 = __fdividef(f2, 1.0f + fabsf(f2));
            float e3 = __fdividef(f3, 1.0f + fabsf(f3));
            float sA = stp[8 * t + c0], sB = stp[8 * t + c0 + 1];
            ds0 += e0 * sA + e1 * sB;
            ds1 += e2 * sA + e3 * sB;
            int kt = t >> 1, hh = (t & 1) * 2;
            eh[kt][hh]     = hi2(e0, e1);
            eh[kt][hh + 1] = hi2(e2, e3);
            el[kt][hh]     = lo2(e0, e1);
            el[kt][hh + 1] = lo2(e2, e3);
        }

        // ---- Phase B: dval[16 x 256] += E @ Vj, K = 32, 3-term split ----
        #pragma unroll
        for (int kt = 0; kt < 2; kt++) {
            uint32_t tb = vjT + kt * (16 * ROWB);
            #pragma unroll
            for (int nt2 = 0; nt2 < 16; nt2++) {
                uint32_t bh[4], bl[4];
                ldm_x4_t(bh, tb + nt2 * 32);
                ldm_x4_t(bl, tb + VJ_LO + nt2 * 32);
                mma16816(dacc[2 * nt2],     eh[kt], bh + 0);
                mma16816(dacc[2 * nt2],     eh[kt], bl + 0);
                mma16816(dacc[2 * nt2],     el[kt], bh + 0);
                mma16816(dacc[2 * nt2 + 1], eh[kt], bh + 2);
                mma16816(dacc[2 * nt2 + 1], eh[kt], bl + 2);
                mma16816(dacc[2 * nt2 + 1], el[kt], bh + 2);
            }
        }
        __syncthreads();     // all reads of buf[h&1] done before iter h+1 refills it
    }

    // ---- write dval ----
    {
        const int row = i0 + mrow + (l >> 2);
        float* d0 = dval + (size_t)b * NN * DD + (size_t)row * DD;
        float* d1 = d0 + 8 * DD;
        #pragma unroll
        for (int nt = 0; nt < 32; nt++) {
            int c = 8 * nt + c0;
            *(float2*)(d0 + c) = make_float2(dacc[nt][0], dacc[nt][1]);
            *(float2*)(d1 + c) = make_float2(dacc[nt][2], dacc[nt][3]);
        }
    }
    // ---- dstate: reduce over the 4 lanes sharing a row ----
    ds0 += __shfl_xor_sync(0xFFFFFFFFu, ds0, 1);
    ds0 += __shfl_xor_sync(0xFFFFFFFFu, ds0, 2);
    ds1 += __shfl_xor_sync(0xFFFFFFFFu, ds1, 1);
    ds1 += __shfl_xor_sync(0xFFFFFFFFu, ds1, 2);
    if ((l & 3) == 0) {
        int r = i0 + mrow + (l >> 2);
        dstate[(size_t)b * NN + r]     = ds0;
        dstate[(size_t)b * NN + r + 8] = ds1;
    }
}

extern "C" void kernel_launch(void* const* d_in, const int* in_sizes, int n_in,
                              void* d_out, int out_size)
{
    const float* val   = (const float*)d_in[0];   // [B, N, D]
    const float* state = (const float*)d_in[1];   // [B, N]
    float* dstate = (float*)d_out;                // [B, N]
    float* dval   = dstate + (size_t)BATCH * NN;  // [B, N, D]
    (void)in_sizes; (void)n_in; (void)out_size;

    dim3 gs(NN / 64, BATCH);
    split_kernel<<<gs, 256>>>(val);

    cudaFuncSetAttribute(prop_hmma,
                         cudaFuncAttributeMaxDynamicSharedMemorySize, (int)SMEM_BYTES);
    dim3 grid(NN / BM, BATCH);
    prop_hmma<<<grid, THREADS, SMEM_BYTES>>>(state, dstate, dval);
}